// round 13
// baseline (speedup 1.0000x reference)
#include <cuda_runtime.h>
#include <cstddef>

#define BATCH   8
#define T_LEN   4096
#define HC      256
#define HD      512
#define NROWS   (BATCH * T_LEN)
#define PD      4
#define NCHUNK  32

// dynamic smem layout (bytes)
#define SM_MBAR   0                    // 2 x 8B
#define SM_STAGE  16                   // 64 floats
#define SM_HBUF   272                  // 2 x 512 floats
#define SM_RING   4368                 // 8 slots x 512 floats
#define SM_WS     20752                // 64 rows x WS_PITCH floats
#define WS_PITCH  516
#define SMEM_TOTAL (SM_WS + 64 * WS_PITCH * 4)   // 152848 B

__device__ float g_wx[NROWS * HD];     // layer-0 input projection
__device__ float g_h0[NROWS * HD];     // layer-0 hidden states
__device__ unsigned g_flags[64];       // h0 chunk progress per (b, rank)

// ---------------------------------------------------------------- helpers
static __device__ __forceinline__ unsigned su32(const void* p) {
    return (unsigned)__cvta_generic_to_shared(p);
}
static __device__ __forceinline__ unsigned long long packf2(float lo, float hi) {
    unsigned long long r;
    asm("mov.b64 %0, {%1, %2};" : "=l"(r) : "f"(lo), "f"(hi));
    return r;
}
static __device__ __forceinline__ void unpackf2(unsigned long long v, float& lo, float& hi) {
    asm("mov.b64 {%0, %1}, %2;" : "=f"(lo), "=f"(hi) : "l"(v));
}
static __device__ __forceinline__ float hw_tanh(float x) {
    float y;
    asm("tanh.approx.f32 %0, %1;" : "=f"(y) : "f"(x));
    return y;
}
static __device__ __forceinline__ void mbar_wait(unsigned addr, unsigned parity) {
    asm volatile(
        "{\n\t.reg .pred P;\n"
        "LW_%=:\n\t"
        "mbarrier.try_wait.parity.acquire.cluster.shared::cta.b64 P, [%0], %1, 0x989680;\n\t"
        "@P bra LD_%=;\n\t"
        "bra LW_%=;\n"
        "LD_%=:\n\t}"
        :: "r"(addr), "r"(parity) : "memory");
}
static __device__ __forceinline__ unsigned ld_acq(const unsigned* p) {
    unsigned v;
    asm volatile("ld.acquire.gpu.global.u32 %0, [%1];" : "=r"(v) : "l"(p) : "memory");
    return v;
}
static __device__ __forceinline__ void st_rel(unsigned* p, unsigned v) {
    asm volatile("st.release.gpu.global.u32 [%0], %1;" :: "l"(p), "r"(v) : "memory");
}
static __device__ __forceinline__ void cp16(unsigned dst, const void* src) {
    asm volatile("cp.async.cg.shared.global [%0], [%1], 16;"
                 :: "r"(dst), "l"(src) : "memory");
}

// ---------------------------------------------------------------------------
// Projection GEMM (layer 0 only, unchanged)
// ---------------------------------------------------------------------------
__global__ __launch_bounds__(256) void proj_kernel(
    const float* __restrict__ X,
    const float* __restrict__ wr, const float* __restrict__ wi,
    const float* __restrict__ br, const float* __restrict__ bi,
    float* __restrict__ Y)
{
    __shared__ float As[16][132];
    __shared__ float Bs[16][132];

    const int bm  = blockIdx.x * 128;
    const int bn  = blockIdx.y * 128;
    const int tid = threadIdx.x;
    const int tx  = tid & 15;
    const int ty  = tid >> 4;
    const int am  = tid >> 1;
    const int ak  = (tid & 1) * 8;
    const int bk  = tid >> 4;
    const int bj  = (tid & 15) * 8;
    const bool jhi = (bn + bj) >= 256;
    const int  jj  = (bn + bj) & 255;

    float acc[8][8];
#pragma unroll
    for (int r = 0; r < 8; ++r)
#pragma unroll
        for (int c = 0; c < 8; ++c) acc[r][c] = 0.f;

    for (int k0 = 0; k0 < HD; k0 += 16) {
        const float* xrow = X + (size_t)(bm + am) * HD + k0 + ak;
        float4 a0 = *(const float4*)(xrow);
        float4 a1 = *(const float4*)(xrow + 4);
        As[ak + 0][am] = a0.x; As[ak + 1][am] = a0.y;
        As[ak + 2][am] = a0.z; As[ak + 3][am] = a0.w;
        As[ak + 4][am] = a1.x; As[ak + 5][am] = a1.y;
        As[ak + 6][am] = a1.z; As[ak + 7][am] = a1.w;
        {
            int k = k0 + bk;
            float4 b0, b1;
            if (k < 256) {
                const float* src = (jhi ? wi : wr) + (size_t)k * 256 + jj;
                b0 = *(const float4*)(src);
                b1 = *(const float4*)(src + 4);
            } else {
                const float* src = (jhi ? wr : wi) + (size_t)(k - 256) * 256 + jj;
                b0 = *(const float4*)(src);
                b1 = *(const float4*)(src + 4);
                if (!jhi) {
                    b0.x = -b0.x; b0.y = -b0.y; b0.z = -b0.z; b0.w = -b0.w;
                    b1.x = -b1.x; b1.y = -b1.y; b1.z = -b1.z; b1.w = -b1.w;
                }
            }
            *(float4*)&Bs[bk][bj]     = b0;
            *(float4*)&Bs[bk][bj + 4] = b1;
        }
        __syncthreads();
#pragma unroll
        for (int kk = 0; kk < 16; ++kk) {
            float4 av0 = *(const float4*)&As[kk][ty * 8];
            float4 av1 = *(const float4*)&As[kk][ty * 8 + 4];
            float4 bv0 = *(const float4*)&Bs[kk][tx * 8];
            float4 bv1 = *(const float4*)&Bs[kk][tx * 8 + 4];
            float a[8] = {av0.x, av0.y, av0.z, av0.w, av1.x, av1.y, av1.z, av1.w};
            float b[8] = {bv0.x, bv0.y, bv0.z, bv0.w, bv1.x, bv1.y, bv1.z, bv1.w};
#pragma unroll
            for (int r = 0; r < 8; ++r)
#pragma unroll
                for (int c = 0; c < 8; ++c)
                    acc[r][c] = fmaf(a[r], b[c], acc[r][c]);
        }
        __syncthreads();
    }

    const int col0 = bn + tx * 8;
    float bias[8];
#pragma unroll
    for (int c = 0; c < 8; ++c) {
        int j = col0 + c;
        bias[c] = (j < 256) ? br[j] : bi[j - 256];
    }
#pragma unroll
    for (int r = 0; r < 8; ++r) {
        float* yrow = Y + (size_t)(bm + ty * 8 + r) * HD + col0;
        *(float4*)(yrow)     = make_float4(acc[r][0]+bias[0], acc[r][1]+bias[1],
                                           acc[r][2]+bias[2], acc[r][3]+bias[3]);
        *(float4*)(yrow + 4) = make_float4(acc[r][4]+bias[4], acc[r][5]+bias[5],
                                           acc[r][6]+bias[6], acc[r][7]+bias[7]);
    }
}

// ---------------------------------------------------------------------------
// Layer-0 scan body (R9, proven) + per-chunk flag publish.
// ---------------------------------------------------------------------------
static __device__ void scan_l0(
    char* dsm, unsigned rank, int b,
    const float* __restrict__ wx,
    const float* __restrict__ ur, const float* __restrict__ ui,
    const float* __restrict__ ubr, const float* __restrict__ ubi,
    float* __restrict__ out, unsigned* flags)
{
    float* hbuf  = (float*)(dsm + SM_HBUF);
    float* stage = (float*)(dsm + SM_STAGE);
    const unsigned hb_u32 = su32(hbuf);
    const unsigned st_u32 = su32(stage);
    const unsigned mb_u32 = su32(dsm + SM_MBAR);

    const int tid  = threadIdx.x;
    const int lane = tid & 31;
    const int jg   = tid >> 4;
    const int kg   = tid & 15;
    const int j0   = (int)rank * 64 + jg * 4;
    const int jj   = j0 & 255;
    const bool jhi = j0 >= 256;

    unsigned dsth_l, dstm_l;
    {
        const int d = tid & 7;
        asm("mapa.shared::cluster.u32 %0, %1, %2;" : "=r"(dsth_l) : "r"(hb_u32), "r"(d));
        asm("mapa.shared::cluster.u32 %0, %1, %2;" : "=r"(dstm_l) : "r"(mb_u32), "r"(d));
    }
    const unsigned dst_slot = dsth_l + (unsigned)(rank * 256);

    unsigned long long w2[4][16];
#pragma unroll
    for (int q = 0; q < 8; ++q) {
        const int k = q * 64 + kg * 4;
        float4 r0, r1, r2, r3;
        if (k < 256) {
            const float* src = (jhi ? ui : ur) + (size_t)k * 256 + jj;
            r0 = *(const float4*)(src);
            r1 = *(const float4*)(src + 256);
            r2 = *(const float4*)(src + 512);
            r3 = *(const float4*)(src + 768);
        } else {
            const float* src = (jhi ? ur : ui) + (size_t)(k - 256) * 256 + jj;
            const float s = jhi ? 1.f : -1.f;
            r0 = *(const float4*)(src);
            r1 = *(const float4*)(src + 256);
            r2 = *(const float4*)(src + 512);
            r3 = *(const float4*)(src + 768);
            r0.x *= s; r0.y *= s; r0.z *= s; r0.w *= s;
            r1.x *= s; r1.y *= s; r1.z *= s; r1.w *= s;
            r2.x *= s; r2.y *= s; r2.z *= s; r2.w *= s;
            r3.x *= s; r3.y *= s; r3.z *= s; r3.w *= s;
        }
        w2[0][2*q]   = packf2(r0.x, r1.x);
        w2[1][2*q]   = packf2(r0.y, r1.y);
        w2[2][2*q]   = packf2(r0.z, r1.z);
        w2[3][2*q]   = packf2(r0.w, r1.w);
        w2[0][2*q+1] = packf2(r2.x, r3.x);
        w2[1][2*q+1] = packf2(r2.y, r3.y);
        w2[2][2*q+1] = packf2(r2.z, r3.z);
        w2[3][2*q+1] = packf2(r2.w, r3.w);
    }
    const float4 ub = jhi ? *(const float4*)(ubi + jj)
                          : *(const float4*)(ubr + jj);

    const float* wx_b  = wx  + (size_t)b * (T_LEN * HD);
    float*       out_b = out + (size_t)b * (T_LEN * HD);
    unsigned* my_flag  = flags + b * 8 + rank;

    const bool is_stage_lane = ((lane & 15) == 0);
    const bool is_out_lane   = ((lane & 15) == 8);

    // t = 0
    {
        float4 wv = *(const float4*)(wx_b + j0);
        wv.x += ub.x; wv.y += ub.y; wv.z += ub.z; wv.w += ub.w;
        if (is_stage_lane | is_out_lane) {
            float4 yv;
            yv.x = hw_tanh(wv.x); yv.y = hw_tanh(wv.y);
            yv.z = hw_tanh(wv.z); yv.w = hw_tanh(wv.w);
            if (is_stage_lane) *(float4*)&stage[jg * 4] = yv;
            else               *(float4*)(out_b + j0) = yv;
        }
        __syncthreads();
        if (tid < 8) {
            asm volatile("fence.proxy.async.shared::cta;" ::: "memory");
            asm volatile(
                "cp.async.bulk.shared::cluster.shared::cta.mbarrier::complete_tx::bytes "
                "[%0], [%1], %2, [%3];"
                :: "r"(dst_slot), "r"(st_u32), "r"(256u), "r"(dstm_l)
                : "memory");
        }
    }

    for (int t = 1; t < T_LEN; ++t) {
        float4 wv = *(const float4*)(wx_b + (size_t)t * HD + j0);
        wv.x += ub.x; wv.y += ub.y; wv.z += ub.z; wv.w += ub.w;

        const int use  = t - 1;
        const int rbuf = use & 1;
        mbar_wait(mb_u32 + rbuf * 8, (unsigned)((use >> 1) & 1));

        if (tid == 0) {
            asm volatile("mbarrier.arrive.expect_tx.shared::cta.b64 _, [%0], %1;"
                         :: "r"(mb_u32 + rbuf * 8), "r"(2048u) : "memory");
        }

        unsigned long long h2[16];
        const float* hp = hbuf + rbuf * HD;
#pragma unroll
        for (int q = 0; q < 8; ++q) {
            ulonglong2 v = *(const ulonglong2*)(hp + q * 64 + kg * 4);
            h2[2*q]   = v.x;
            h2[2*q+1] = v.y;
        }

        unsigned long long acc0 = 0, acc1 = 0, acc2 = 0, acc3 = 0;
#pragma unroll
        for (int q = 0; q < 16; ++q) {
            asm("fma.rn.f32x2 %0, %1, %2, %0;" : "+l"(acc0) : "l"(h2[q]), "l"(w2[0][q]));
            asm("fma.rn.f32x2 %0, %1, %2, %0;" : "+l"(acc1) : "l"(h2[q]), "l"(w2[1][q]));
            asm("fma.rn.f32x2 %0, %1, %2, %0;" : "+l"(acc2) : "l"(h2[q]), "l"(w2[2][q]));
            asm("fma.rn.f32x2 %0, %1, %2, %0;" : "+l"(acc3) : "l"(h2[q]), "l"(w2[3][q]));
        }
        float a0, a1, a2, a3, hq;
        unpackf2(acc0, a0, hq); a0 += hq;
        unpackf2(acc1, a1, hq); a1 += hq;
        unpackf2(acc2, a2, hq); a2 += hq;
        unpackf2(acc3, a3, hq); a3 += hq;
#pragma unroll
        for (int off = 1; off < 16; off <<= 1) {
            a0 += __shfl_xor_sync(0xffffffffu, a0, off);
            a1 += __shfl_xor_sync(0xffffffffu, a1, off);
            a2 += __shfl_xor_sync(0xffffffffu, a2, off);
            a3 += __shfl_xor_sync(0xffffffffu, a3, off);
        }

        if (is_stage_lane | is_out_lane) {
            float4 yv;
            yv.x = hw_tanh(wv.x + a0);
            yv.y = hw_tanh(wv.y + a1);
            yv.z = hw_tanh(wv.z + a2);
            yv.w = hw_tanh(wv.w + a3);
            if (is_stage_lane) {
                if (t < T_LEN - 1) *(float4*)&stage[jg * 4] = yv;
            } else {
                *(float4*)(out_b + (size_t)t * HD + j0) = yv;
            }
        }

        if (t < T_LEN - 1) {
            __syncthreads();
            if (tid < 8) {
                const unsigned boff = (unsigned)((t & 1) * 2048);
                const unsigned moff = (unsigned)((t & 1) * 8);
                asm volatile("fence.proxy.async.shared::cta;" ::: "memory");
                asm volatile(
                    "cp.async.bulk.shared::cluster.shared::cta.mbarrier::complete_tx::bytes "
                    "[%0], [%1], %2, [%3];"
                    :: "r"(dst_slot + boff), "r"(st_u32), "r"(256u), "r"(dstm_l + moff)
                    : "memory");
            }
            // publish h0 chunk progress (stores ordered by __syncthreads above)
            if (tid == 0 && (t & 127) == 127) {
                st_rel(my_flag, (unsigned)((t >> 7) + 1));
            }
        }
    }
    __syncthreads();
    if (tid == 0) st_rel(my_flag, (unsigned)NCHUNK);
}

// ---------------------------------------------------------------------------
// Layer-1 fused scan: h1_t = tanh(b1 + W1*h0_t + U1*h1_{t-1}).
// U1 slice in registers (as L0). W1 slice in SMEM [64 x 516 pitch].
// h0 streamed from global via cp.async ring (PD ahead), gated by L0 chunk
// flags. W1*h0[t+1] partials computed one step AHEAD (in exchange slack) and
// used to initialize the accumulators at step t+1 — same kg distribution, so
// the single shfl reduce covers both matvecs.
// ---------------------------------------------------------------------------
static __device__ void scan_l1(
    char* dsm, unsigned rank, int b,
    const float* __restrict__ wr, const float* __restrict__ wi,
    const float* __restrict__ wbr, const float* __restrict__ wbi,
    const float* __restrict__ ur, const float* __restrict__ ui,
    const float* __restrict__ ubr, const float* __restrict__ ubi,
    const float* __restrict__ h0, float* __restrict__ out, unsigned* flags)
{
    float* hbuf  = (float*)(dsm + SM_HBUF);
    float* stage = (float*)(dsm + SM_STAGE);
    float* ring  = (float*)(dsm + SM_RING);
    float* Ws    = (float*)(dsm + SM_WS);
    const unsigned hb_u32 = su32(hbuf);
    const unsigned st_u32 = su32(stage);
    const unsigned mb_u32 = su32(dsm + SM_MBAR);
    const unsigned rg_u32 = su32(ring);

    const int tid  = threadIdx.x;
    const int lane = tid & 31;
    const int jg   = tid >> 4;
    const int kg   = tid & 15;
    const int j0   = (int)rank * 64 + jg * 4;
    const int jj   = j0 & 255;
    const bool jhi = j0 >= 256;
    const int  jjbase = ((int)rank * 64) & 255;

    unsigned dsth_l, dstm_l;
    {
        const int d = tid & 7;
        asm("mapa.shared::cluster.u32 %0, %1, %2;" : "=r"(dsth_l) : "r"(hb_u32), "r"(d));
        asm("mapa.shared::cluster.u32 %0, %1, %2;" : "=r"(dstm_l) : "r"(mb_u32), "r"(d));
    }
    const unsigned dst_slot = dsth_l + (unsigned)(rank * 256);

    // ---- U1 slice into registers ----
    unsigned long long w2[4][16];
#pragma unroll
    for (int q = 0; q < 8; ++q) {
        const int k = q * 64 + kg * 4;
        float4 r0, r1, r2, r3;
        if (k < 256) {
            const float* src = (jhi ? ui : ur) + (size_t)k * 256 + jj;
            r0 = *(const float4*)(src);
            r1 = *(const float4*)(src + 256);
            r2 = *(const float4*)(src + 512);
            r3 = *(const float4*)(src + 768);
        } else {
            const float* src = (jhi ? ur : ui) + (size_t)(k - 256) * 256 + jj;
            const float s = jhi ? 1.f : -1.f;
            r0 = *(const float4*)(src);
            r1 = *(const float4*)(src + 256);
            r2 = *(const float4*)(src + 512);
            r3 = *(const float4*)(src + 768);
            r0.x *= s; r0.y *= s; r0.z *= s; r0.w *= s;
            r1.x *= s; r1.y *= s; r1.z *= s; r1.w *= s;
            r2.x *= s; r2.y *= s; r2.z *= s; r2.w *= s;
            r3.x *= s; r3.y *= s; r3.z *= s; r3.w *= s;
        }
        w2[0][2*q]   = packf2(r0.x, r1.x);
        w2[1][2*q]   = packf2(r0.y, r1.y);
        w2[2][2*q]   = packf2(r0.z, r1.z);
        w2[3][2*q]   = packf2(r0.w, r1.w);
        w2[0][2*q+1] = packf2(r2.x, r3.x);
        w2[1][2*q+1] = packf2(r2.y, r3.y);
        w2[2][2*q+1] = packf2(r2.z, r3.z);
        w2[3][2*q+1] = packf2(r2.w, r3.w);
    }
    // combined bias b1 (recurrent bias ub1 is zero-init in reference but add
    // both anyway: total bias = wb + ub)
    float4 ub;
    {
        float4 u1 = jhi ? *(const float4*)(ubi + jj) : *(const float4*)(ubr + jj);
        float4 w1 = jhi ? *(const float4*)(wbi + jj) : *(const float4*)(wbr + jj);
        ub.x = u1.x + w1.x; ub.y = u1.y + w1.y;
        ub.z = u1.z + w1.z; ub.w = u1.w + w1.w;
    }

    // ---- W1 slice into SMEM: Ws[j][k], j local 0..63, pitch 516 ----
    for (int it = tid; it < 512 * 16; it += 256) {
        const int k  = it >> 4;
        const int j4 = (it & 15) * 4;
        float4 v; float sgn;
        if (k < 256) {
            v = *(const float4*)((jhi ? wi : wr) + (size_t)k * 256 + jjbase + j4);
            sgn = 1.f;
        } else {
            v = *(const float4*)((jhi ? wr : wi) + (size_t)(k - 256) * 256 + jjbase + j4);
            sgn = jhi ? 1.f : -1.f;
        }
        Ws[(j4 + 0) * WS_PITCH + k] = v.x * sgn;
        Ws[(j4 + 1) * WS_PITCH + k] = v.y * sgn;
        Ws[(j4 + 2) * WS_PITCH + k] = v.z * sgn;
        Ws[(j4 + 3) * WS_PITCH + k] = v.w * sgn;
    }

    const float* h0_b  = h0  + (size_t)b * (T_LEN * HD);
    float*       out_b = out + (size_t)b * (T_LEN * HD);
    const unsigned* bflags = flags + b * 8;

    // ---- gate chunk 0 + prologue prefetch slots 0..PD-1 ----
    if (tid < 8) {
        while (ld_acq(bflags + tid) < 1u) __nanosleep(256);
    }
    __syncthreads();
    if (tid < 128) {
#pragma unroll
        for (int s = 0; s < PD; ++s) {
            cp16(rg_u32 + (unsigned)(s * 2048 + tid * 16),
                 h0_b + (size_t)s * HD + tid * 4);
            asm volatile("cp.async.commit_group;" ::: "memory");
        }
        asm volatile("cp.async.wait_group %0;" :: "n"(PD - 1) : "memory");
    }
    __syncthreads();

    const bool is_stage_lane = ((lane & 15) == 0);
    const bool is_out_lane   = ((lane & 15) == 8);

    // ---- W1 partial for step 0 ----
    unsigned long long aW0, aW1, aW2, aW3;
    {
        const float* h0s = ring;  // slot 0
        unsigned long long hh[16];
#pragma unroll
        for (int q = 0; q < 8; ++q) {
            ulonglong2 v = *(const ulonglong2*)(h0s + q * 64 + kg * 4);
            hh[2*q] = v.x; hh[2*q+1] = v.y;
        }
        unsigned long long t0 = 0, t1 = 0, t2 = 0, t3 = 0;
#pragma unroll
        for (int q = 0; q < 8; ++q) {
            const int koff = q * 64 + kg * 4;
            ulonglong2 wv0 = *(const ulonglong2*)(Ws + (jg*4 + 0) * WS_PITCH + koff);
            ulonglong2 wv1 = *(const ulonglong2*)(Ws + (jg*4 + 1) * WS_PITCH + koff);
            ulonglong2 wv2 = *(const ulonglong2*)(Ws + (jg*4 + 2) * WS_PITCH + koff);
            ulonglong2 wv3 = *(const ulonglong2*)(Ws + (jg*4 + 3) * WS_PITCH + koff);
            asm("fma.rn.f32x2 %0, %1, %2, %0;" : "+l"(t0) : "l"(hh[2*q]),   "l"(wv0.x));
            asm("fma.rn.f32x2 %0, %1, %2, %0;" : "+l"(t0) : "l"(hh[2*q+1]), "l"(wv0.y));
            asm("fma.rn.f32x2 %0, %1, %2, %0;" : "+l"(t1) : "l"(hh[2*q]),   "l"(wv1.x));
            asm("fma.rn.f32x2 %0, %1, %2, %0;" : "+l"(t1) : "l"(hh[2*q+1]), "l"(wv1.y));
            asm("fma.rn.f32x2 %0, %1, %2, %0;" : "+l"(t2) : "l"(hh[2*q]),   "l"(wv2.x));
            asm("fma.rn.f32x2 %0, %1, %2, %0;" : "+l"(t2) : "l"(hh[2*q+1]), "l"(wv2.y));
            asm("fma.rn.f32x2 %0, %1, %2, %0;" : "+l"(t3) : "l"(hh[2*q]),   "l"(wv3.x));
            asm("fma.rn.f32x2 %0, %1, %2, %0;" : "+l"(t3) : "l"(hh[2*q+1]), "l"(wv3.y));
        }
        aW0 = t0; aW1 = t1; aW2 = t2; aW3 = t3;
    }

    for (int t = 0; t < T_LEN; ++t) {
        unsigned long long acc0 = aW0, acc1 = aW1, acc2 = aW2, acc3 = aW3;

        if (t > 0) {
            const int use  = t - 1;
            const int rbuf = use & 1;
            mbar_wait(mb_u32 + rbuf * 8, (unsigned)((use >> 1) & 1));
            if (tid == 0) {
                asm volatile("mbarrier.arrive.expect_tx.shared::cta.b64 _, [%0], %1;"
                             :: "r"(mb_u32 + rbuf * 8), "r"(2048u) : "memory");
            }
            unsigned long long h2[16];
            const float* hp = hbuf + rbuf * HD;
#pragma unroll
            for (int q = 0; q < 8; ++q) {
                ulonglong2 v = *(const ulonglong2*)(hp + q * 64 + kg * 4);
                h2[2*q] = v.x; h2[2*q+1] = v.y;
            }
#pragma unroll
            for (int q = 0; q < 16; ++q) {
                asm("fma.rn.f32x2 %0, %1, %2, %0;" : "+l"(acc0) : "l"(h2[q]), "l"(w2[0][q]));
                asm("fma.rn.f32x2 %0, %1, %2, %0;" : "+l"(acc1) : "l"(h2[q]), "l"(w2[1][q]));
                asm("fma.rn.f32x2 %0, %1, %2, %0;" : "+l"(acc2) : "l"(h2[q]), "l"(w2[2][q]));
                asm("fma.rn.f32x2 %0, %1, %2, %0;" : "+l"(acc3) : "l"(h2[q]), "l"(w2[3][q]));
            }
        }

        float a0, a1, a2, a3, hq;
        unpackf2(acc0, a0, hq); a0 += hq;
        unpackf2(acc1, a1, hq); a1 += hq;
        unpackf2(acc2, a2, hq); a2 += hq;
        unpackf2(acc3, a3, hq); a3 += hq;
#pragma unroll
        for (int off = 1; off < 16; off <<= 1) {
            a0 += __shfl_xor_sync(0xffffffffu, a0, off);
            a1 += __shfl_xor_sync(0xffffffffu, a1, off);
            a2 += __shfl_xor_sync(0xffffffffu, a2, off);
            a3 += __shfl_xor_sync(0xffffffffu, a3, off);
        }

        if (is_stage_lane | is_out_lane) {
            float4 yv;
            yv.x = hw_tanh(ub.x + a0);
            yv.y = hw_tanh(ub.y + a1);
            yv.z = hw_tanh(ub.z + a2);
            yv.w = hw_tanh(ub.w + a3);
            if (is_stage_lane) {
                if (t < T_LEN - 1) *(float4*)&stage[jg * 4] = yv;
            } else {
                *(float4*)(out_b + (size_t)t * HD + j0) = yv;
            }
        }

        if (t < T_LEN - 1) {
            // prefetch h0[t+PD] (gated once per chunk boundary)
            const int tp = t + PD;
            if (tp < T_LEN) {
                if ((tp & 127) == 0) {
                    if (tid < 8) {
                        const unsigned need = (unsigned)((tp >> 7) + 1);
                        while (ld_acq(bflags + tid) < need) __nanosleep(128);
                    }
                    __syncthreads();
                }
                if (tid < 128) {
                    cp16(rg_u32 + (unsigned)((tp & 7) * 2048 + tid * 16),
                         h0_b + (size_t)tp * HD + tid * 4);
                    asm volatile("cp.async.commit_group;" ::: "memory");
                }
            }
            if (tid < 128) {
                asm volatile("cp.async.wait_group %0;" :: "n"(PD - 1) : "memory");
            }
            __syncthreads();
            if (tid < 8) {
                const unsigned boff = (unsigned)((t & 1) * 2048);
                const unsigned moff = (unsigned)((t & 1) * 8);
                asm volatile("fence.proxy.async.shared::cta;" ::: "memory");
                asm volatile(
                    "cp.async.bulk.shared::cluster.shared::cta.mbarrier::complete_tx::bytes "
                    "[%0], [%1], %2, [%3];"
                    :: "r"(dst_slot + boff), "r"(st_u32), "r"(256u), "r"(dstm_l + moff)
                    : "memory");
            }

            // ---- W1 partial for step t+1 (overlaps the exchange) ----
            {
                const float* h0s = ring + ((t + 1) & 7) * HD;
                unsigned long long hh[16];
#pragma unroll
                for (int q = 0; q < 8; ++q) {
                    ulonglong2 v = *(const ulonglong2*)(h0s + q * 64 + kg * 4);
                    hh[2*q] = v.x; hh[2*q+1] = v.y;
                }
                unsigned long long t0 = 0, t1 = 0, t2 = 0, t3 = 0;
#pragma unroll
                for (int q = 0; q < 8; ++q) {
                    const int koff = q * 64 + kg * 4;
                    ulonglong2 wv0 = *(const ulonglong2*)(Ws + (jg*4 + 0) * WS_PITCH + koff);
                    ulonglong2 wv1 = *(const ulonglong2*)(Ws + (jg*4 + 1) * WS_PITCH + koff);
                    ulonglong2 wv2 = *(const ulonglong2*)(Ws + (jg*4 + 2) * WS_PITCH + koff);
                    ulonglong2 wv3 = *(const ulonglong2*)(Ws + (jg*4 + 3) * WS_PITCH + koff);
                    asm("fma.rn.f32x2 %0, %1, %2, %0;" : "+l"(t0) : "l"(hh[2*q]),   "l"(wv0.x));
                    asm("fma.rn.f32x2 %0, %1, %2, %0;" : "+l"(t0) : "l"(hh[2*q+1]), "l"(wv0.y));
                    asm("fma.rn.f32x2 %0, %1, %2, %0;" : "+l"(t1) : "l"(hh[2*q]),   "l"(wv1.x));
                    asm("fma.rn.f32x2 %0, %1, %2, %0;" : "+l"(t1) : "l"(hh[2*q+1]), "l"(wv1.y));
                    asm("fma.rn.f32x2 %0, %1, %2, %0;" : "+l"(t2) : "l"(hh[2*q]),   "l"(wv2.x));
                    asm("fma.rn.f32x2 %0, %1, %2, %0;" : "+l"(t2) : "l"(hh[2*q+1]), "l"(wv2.y));
                    asm("fma.rn.f32x2 %0, %1, %2, %0;" : "+l"(t3) : "l"(hh[2*q]),   "l"(wv3.x));
                    asm("fma.rn.f32x2 %0, %1, %2, %0;" : "+l"(t3) : "l"(hh[2*q+1]), "l"(wv3.y));
                }
                aW0 = t0; aW1 = t1; aW2 = t2; aW3 = t3;
            }
        }
    }
}

// ---------------------------------------------------------------------------
__global__ void __cluster_dims__(8, 1, 1) __launch_bounds__(256, 1)
fused_scan(const float* __restrict__ wx0,
           const float* __restrict__ l0_ur, const float* __restrict__ l0_ui,
           const float* __restrict__ l0_ubr, const float* __restrict__ l0_ubi,
           const float* __restrict__ l1_wr, const float* __restrict__ l1_wi,
           const float* __restrict__ l1_wbr, const float* __restrict__ l1_wbi,
           const float* __restrict__ l1_ur, const float* __restrict__ l1_ui,
           const float* __restrict__ l1_ubr, const float* __restrict__ l1_ubi,
           float* h0, float* out, unsigned* flags)
{
    extern __shared__ char dsm[];
    unsigned rank;
    asm("mov.u32 %0, %%cluster_ctarank;" : "=r"(rank));
    const int tid = threadIdx.x;
    const int cl  = blockIdx.x >> 3;

    if (tid == 0) {
        const unsigned mb = su32(dsm + SM_MBAR);
        asm volatile("mbarrier.init.shared.b64 [%0], %1;" :: "r"(mb),     "r"(1u) : "memory");
        asm volatile("mbarrier.init.shared.b64 [%0], %1;" :: "r"(mb + 8), "r"(1u) : "memory");
        asm volatile("mbarrier.arrive.expect_tx.shared::cta.b64 _, [%0], %1;"
                     :: "r"(mb),     "r"(2048u) : "memory");
        asm volatile("mbarrier.arrive.expect_tx.shared::cta.b64 _, [%0], %1;"
                     :: "r"(mb + 8), "r"(2048u) : "memory");
    }
    __syncthreads();
    asm volatile("barrier.cluster.arrive.aligned;" ::: "memory");
    asm volatile("barrier.cluster.wait.aligned;"   ::: "memory");

    if (cl < 8) {
        scan_l0(dsm, rank, cl, wx0, l0_ur, l0_ui, l0_ubr, l0_ubi, h0, flags);
    } else {
        scan_l1(dsm, rank, cl - 8, l1_wr, l1_wi, l1_wbr, l1_wbi,
                l1_ur, l1_ui, l1_ubr, l1_ubi, h0, out, flags);
    }

    asm volatile("barrier.cluster.arrive;" ::: "memory");
    asm volatile("barrier.cluster.wait;"   ::: "memory");
}

// ---------------------------------------------------------------------------
extern "C" void kernel_launch(void* const* d_in, const int* in_sizes, int n_in,
                              void* d_out, int out_size)
{
    const float* x      = (const float*)d_in[0];
    const float* l0_wr  = (const float*)d_in[1];
    const float* l0_wi  = (const float*)d_in[2];
    const float* l0_wbr = (const float*)d_in[3];
    const float* l0_wbi = (const float*)d_in[4];
    const float* l0_ur  = (const float*)d_in[5];
    const float* l0_ui  = (const float*)d_in[6];
    const float* l0_ubr = (const float*)d_in[7];
    const float* l0_ubi = (const float*)d_in[8];
    const float* l1_wr  = (const float*)d_in[9];
    const float* l1_wi  = (const float*)d_in[10];
    const float* l1_wbr = (const float*)d_in[11];
    const float* l1_wbi = (const float*)d_in[12];
    const float* l1_ur  = (const float*)d_in[13];
    const float* l1_ui  = (const float*)d_in[14];
    const float* l1_ubr = (const float*)d_in[15];
    const float* l1_ubi = (const float*)d_in[16];

    float* out = (float*)d_out;

    void *p_wx_v = nullptr, *p_h0_v = nullptr, *p_fl_v = nullptr;
    cudaGetSymbolAddress(&p_wx_v, g_wx);
    cudaGetSymbolAddress(&p_h0_v, g_h0);
    cudaGetSymbolAddress(&p_fl_v, g_flags);
    float* p_wx = (float*)p_wx_v;
    float* p_h0 = (float*)p_h0_v;
    unsigned* p_fl = (unsigned*)p_fl_v;

    cudaFuncSetAttribute(fused_scan,
                         cudaFuncAttributeMaxDynamicSharedMemorySize, SMEM_TOTAL);

    cudaMemsetAsync(p_fl, 0, sizeof(unsigned) * 64);

    dim3 pgrid(NROWS / 128, HD / 128);
    proj_kernel<<<pgrid, 256>>>(x, l0_wr, l0_wi, l0_wbr, l0_wbi, p_wx);

    fused_scan<<<128, 256, SMEM_TOTAL>>>(p_wx,
                                         l0_ur, l0_ui, l0_ubr, l0_ubi,
                                         l1_wr, l1_wi, l1_wbr, l1_wbi,
                                         l1_ur, l1_ui, l1_ubr, l1_ubi,
                                         p_h0, out, p_fl);
}